// round 14
// baseline (speedup 1.0000x reference)
#include <cuda_runtime.h>
#include <cuda_bf16.h>
#include <cstdint>

#define K_DIM 1024
#define E_DIM 64
#define NVEC  65536
#define NPIX  4194304
#define KC    64                  // codes per chunk
#define NCH   (K_DIM / KC)        // 16
#define NCTA  (NVEC / 128)        // 512 CTAs x 256 thr, 128 vec/CTA
#define CAP   3                   // per-(vec,half,quad) bucket capacity
#define MARG  4e-5f               // >> 80x worst-case fp32 reorder error

// SMEM layout (bytes)
#define ZT_OFF   0                // z tile f32 [64][128]            32768
#define ED_OFF   32768            // packed code-pairs ull [64][32]  16384
#define E2_OFF   49152            // e2 chunk f32 [64]                 256
#define Z2_OFF   49408            // z2 f32 [128]                      512
#define CNT_OFF  49920            // uchar [128][8]                   1024
#define BKT_OFF  50944            // uint2 [128][8][CAP]             24576
#define SMEM_TOTAL 75520

__device__ double       d_loss_acc;
__device__ unsigned int d_ticket;
__device__ float        d_e2[K_DIM];
__device__ unsigned long long d_cbP[E_DIM * K_DIM / 2];  // [c][pair j]

typedef unsigned long long ull;

__device__ __forceinline__ void fma2(ull& d, ull a, ull b) {
    asm("fma.rn.f32x2 %0, %1, %2, %0;" : "+l"(d) : "l"(a), "l"(b));
}
__device__ __forceinline__ void add2(ull& d, ull a) {
    asm("add.rn.f32x2 %0, %0, %1;" : "+l"(d) : "l"(a));
}
__device__ __forceinline__ float2 unpack2(ull v) {
    float2 r; asm("mov.b64 {%0, %1}, %2;" : "=f"(r.x), "=f"(r.y) : "l"(v)); return r;
}
__device__ __forceinline__ ull pack2(float lo, float hi) {
    ull v; asm("mov.b64 %0, {%1, %2};" : "=l"(v) : "f"(lo), "f"(hi)); return v;
}
__device__ __forceinline__ ull dup1(float x) {
    ull v; asm("mov.b64 %0, {%1, %1};" : "=l"(v) : "f"(x)); return v;
}

// prep: e2 (proven float4-sequential) + packed-pair transposed codebook
__global__ void prep_kernel(const float* __restrict__ cb) {
    int idx = blockIdx.x * 256 + threadIdx.x;
    if (idx < E_DIM * K_DIM / 2) {
        int c = idx >> 9, j = idx & 511;
        d_cbP[idx] = pack2(cb[(2 * j) * E_DIM + c], cb[(2 * j + 1) * E_DIM + c]);
    }
    if (idx < K_DIM) {
        const float4* r = reinterpret_cast<const float4*>(cb + idx * E_DIM);
        float s = 0.f;
#pragma unroll
        for (int i = 0; i < E_DIM / 4; i++) {
            float4 v = r[i];
            s += v.x * v.x + v.y * v.y + v.z * v.z + v.w * v.w;
        }
        d_e2[idx] = s;
    }
}

// exact distance, bit-identical to the proven R3/R7 kernels.
__device__ __forceinline__ float exact_dist(const float* zt, int v, float z2,
                                            const float* cb, int k) {
    const ulonglong2* ep = reinterpret_cast<const ulonglong2*>(cb + k * E_DIM);
    ull a0 = 0, a1 = 0, a2 = 0, a3 = 0;
#pragma unroll
    for (int i = 0; i < 8; i++) {
        ulonglong2 e0 = ep[2 * i];
        ulonglong2 e1 = ep[2 * i + 1];
        fma2(a0, pack2(zt[(8 * i + 0) * 128 + v], zt[(8 * i + 1) * 128 + v]), e0.x);
        fma2(a1, pack2(zt[(8 * i + 2) * 128 + v], zt[(8 * i + 3) * 128 + v]), e0.y);
        fma2(a2, pack2(zt[(8 * i + 4) * 128 + v], zt[(8 * i + 5) * 128 + v]), e1.x);
        fma2(a3, pack2(zt[(8 * i + 6) * 128 + v], zt[(8 * i + 7) * 128 + v]), e1.y);
    }
    add2(a0, a1); add2(a2, a3); add2(a0, a2);
    float2 s = unpack2(a0);
    float dot = __fadd_rn(s.x, s.y);
    return __fmaf_rn(-2.0f, dot, __fadd_rn(z2, d_e2[k]));
}

__global__ __launch_bounds__(256, 3)
void vq_kernel(const float* __restrict__ z,
               const float* __restrict__ cb,
               float* __restrict__ out_vq,
               float* __restrict__ out_loss,
               int has_loss) {
    extern __shared__ char sm[];
    float* zt  = reinterpret_cast<float*>(sm + ZT_OFF);
    ull*   ed  = reinterpret_cast<ull*>(sm + ED_OFF);
    float* e2s = reinterpret_cast<float*>(sm + E2_OFF);
    float* z2s = reinterpret_cast<float*>(sm + Z2_OFF);
    unsigned char* cnts = reinterpret_cast<unsigned char*>(sm + CNT_OFF);
    uint2* bkt = reinterpret_cast<uint2*>(sm + BKT_OFF);

    const int tid = threadIdx.x, lane = tid & 31, w = tid >> 5;
    const int g = lane >> 2, q = lane & 3;       // vec-group / codepair-group
    const int v4 = w >> 1, w2 = w & 1;           // vec-warpgroup / code-half
    const int V0 = v4 * 32 + g * 4;              // first of my 4 vecs
    const int jb = w2 * 16 + q * 4;              // first of my 4 code-pairs
    const int m0 = blockIdx.x * 128;
    const int base = (m0 >> 12) * (E_DIM * 4096) + (m0 & 4095);

    // ---- prologue: z tile [c][v] ----
    for (int idx = tid; idx < E_DIM * 128; idx += 256)
        zt[idx] = z[base + (idx >> 7) * 4096 + (idx & 127)];
    __syncthreads();
    // z2 per vec (proven pair-sequential order), coalesced across owners.
    if (tid < 128) {
        float s = 0.f;
#pragma unroll
        for (int p = 0; p < 32; p++) {
            float lo = zt[(2 * p) * 128 + tid];
            float hi = zt[(2 * p + 1) * 128 + tid];
            s = __fadd_rn(s, __fadd_rn(__fmul_rn(lo, lo), __fmul_rn(hi, hi)));
        }
        z2s[tid] = s;
    }
    __syncthreads();

    float z2r[4];
#pragma unroll
    for (int i = 0; i < 4; i++) z2r[i] = z2s[V0 + i];

    float best[4];
    int   cnt[4];
#pragma unroll
    for (int i = 0; i < 4; i++) { best[i] = 3.4e38f; cnt[i] = 0; }

    // ---- main loop over 16 chunks ----
#pragma unroll 1
    for (int ch = 0; ch < NCH; ch++) {
        const int k0 = ch * KC;
        __syncthreads();
        for (int i = tid; i < E_DIM * 32; i += 256)        // 16KB chunk
            ed[i] = d_cbP[(i >> 5) * 512 + ch * 32 + (i & 31)];
        if (tid < KC) e2s[tid] = d_e2[k0 + tid];
        __syncthreads();

        ull acc[16];
#pragma unroll
        for (int i = 0; i < 16; i++) acc[i] = 0ull;

#pragma unroll 4
        for (int c = 0; c < E_DIM; c++) {
            float4 zv = *reinterpret_cast<const float4*>(zt + c * 128 + V0);
            ull zd0 = dup1(zv.x), zd1 = dup1(zv.y);
            ull zd2 = dup1(zv.z), zd3 = dup1(zv.w);
            const ulonglong2* eb =
                reinterpret_cast<const ulonglong2*>(ed + c * 32 + jb);
            ulonglong2 e01 = eb[0];
            ulonglong2 e23 = eb[1];
            fma2(acc[0],  zd0, e01.x); fma2(acc[1],  zd0, e01.y);
            fma2(acc[2],  zd0, e23.x); fma2(acc[3],  zd0, e23.y);
            fma2(acc[4],  zd1, e01.x); fma2(acc[5],  zd1, e01.y);
            fma2(acc[6],  zd1, e23.x); fma2(acc[7],  zd1, e23.y);
            fma2(acc[8],  zd2, e01.x); fma2(acc[9],  zd2, e01.y);
            fma2(acc[10], zd2, e23.x); fma2(acc[11], zd2, e23.y);
            fma2(acc[12], zd3, e01.x); fma2(acc[13], zd3, e01.y);
            fma2(acc[14], zd3, e23.x); fma2(acc[15], zd3, e23.y);
        }

        // dist eval + margin bucket push (R6-proven machinery)
#pragma unroll
        for (int j = 0; j < 4; j++) {
            float2 e2v = *reinterpret_cast<const float2*>(e2s + 2 * (jb + j));
            const int kx = k0 + 2 * (jb + j);
#pragma unroll
            for (int vs = 0; vs < 4; vs++) {
                float2 dd = unpack2(acc[vs * 4 + j]);
                float t = z2r[vs];
                float dx = __fmaf_rn(-2.f, dd.x, __fadd_rn(t, e2v.x));
                float dy = __fmaf_rn(-2.f, dd.y, __fadd_rn(t, e2v.y));
#pragma unroll
                for (int h = 0; h < 2; h++) {
                    float d = h ? dy : dx;
                    if (d < best[vs] + MARG) {
                        if (d < best[vs]) best[vs] = d;
                        uint2* b = bkt + ((V0 + vs) * 8 + w2 * 4 + q) * CAP;
                        if (cnt[vs] == CAP) {              // prune stale
                            int wr = 0;
#pragma unroll 1
                            for (int s = 0; s < CAP; s++) {
                                uint2 e = b[s];
                                if (__uint_as_float(e.x) < best[vs] + MARG)
                                    b[wr++] = e;
                            }
                            cnt[vs] = wr;
                            if (wr == CAP) {               // evict max if closer
                                int mi = 0;
                                float mv = __uint_as_float(b[0].x);
#pragma unroll 1
                                for (int s = 1; s < CAP; s++) {
                                    float vv = __uint_as_float(b[s].x);
                                    if (vv > mv) { mv = vv; mi = s; }
                                }
                                if (d < mv)
                                    b[mi] = make_uint2(__float_as_uint(d),
                                                       (uint32_t)(kx + h));
                                continue;
                            }
                        }
                        b[cnt[vs]++] = make_uint2(__float_as_uint(d),
                                                  (uint32_t)(kx + h));
                    }
                }
            }
        }
    }

    // publish counters
#pragma unroll
    for (int vs = 0; vs < 4; vs++)
        cnts[(V0 + vs) * 8 + w2 * 4 + q] = (unsigned char)cnt[vs];
    __syncthreads();

    // ---- owner phase: exact re-rank (proven arithmetic) + epilogue ----
    float local = 0.f;
    if (tid < 128) {
        const int v = tid;
        const float z2v = z2s[v];
        float bE = 3.4e38f;
        int   bK = 0;
#pragma unroll 1
        for (int bq = 0; bq < 8; bq++) {
            int c = cnts[v * 8 + bq];
            const uint2* b = bkt + (v * 8 + bq) * CAP;
#pragma unroll 1
            for (int s = 0; s < c; s++) {
                int k = (int)b[s].y;
                float de = exact_dist(zt, v, z2v, cb, k);
                if (de < bE || (de == bE && k < bK)) { bE = de; bK = k; }
            }
        }
        // gather winner, write vq (coalesced across owners), loss
        const float2* er = reinterpret_cast<const float2*>(cb + bK * E_DIM);
#pragma unroll
        for (int i = 0; i < E_DIM / 2; i++) {
            float2 e = __ldg(&er[i]);
            float p0 = zt[(2 * i) * 128 + v];
            float p1 = zt[(2 * i + 1) * 128 + v];
            float q0 = e.x - p0, q1 = e.y - p1;
            local += q0 * q0 + q1 * q1;
            out_vq[base + (2 * i) * 4096 + v]     = e.x;
            out_vq[base + (2 * i + 1) * 4096 + v] = e.y;
        }
    }
#pragma unroll
    for (int o = 16; o; o >>= 1)
        local += __shfl_xor_sync(0xFFFFFFFFu, local, o);
    if (lane == 0 && w < 4)
        atomicAdd(&d_loss_acc, (double)local);

    __syncthreads();
    if (tid == 0) {
        __threadfence();
        unsigned int done = atomicAdd(&d_ticket, 1u);
        if (done == (unsigned int)(NCTA - 1)) {
            if (has_loss)
                *out_loss = (float)(1.25 * d_loss_acc / (double)NPIX);
            d_loss_acc = 0.0;
            d_ticket   = 0u;
            __threadfence();
        }
    }
}

extern "C" void kernel_launch(void* const* d_in, const int* in_sizes, int n_in,
                              void* d_out, int out_size) {
    const float* z  = (const float*)d_in[0];
    const float* cb = (const float*)d_in[1];
    if (n_in >= 2 && in_sizes[0] == K_DIM * E_DIM && in_sizes[1] == NPIX) {
        const float* t = z; z = cb; cb = t;   // defensive: inputs swapped
    }

    float* out = (float*)d_out;
    int voff = out_size - NPIX;
    if (voff < 0) voff = 0;
    float* out_vq = out + voff;

    cudaFuncSetAttribute(vq_kernel,
                         cudaFuncAttributeMaxDynamicSharedMemorySize, SMEM_TOTAL);

    prep_kernel<<<(E_DIM * K_DIM / 2 + 255) / 256, 256>>>(cb);
    vq_kernel<<<NCTA, 256, SMEM_TOTAL>>>(z, cb, out_vq, out, voff > 0 ? 1 : 0);
}

// round 15
// speedup vs baseline: 1.0109x; 1.0109x over previous
#include <cuda_runtime.h>
#include <cstdint>

#define K_DIM 1024
#define E_DIM 64
#define NVEC  65536
#define NPIX  4194304
#define VB    256                  // vectors per main CTA (2 tiles x 128)
#define NCTA_MAIN ((NVEC / VB) * 2)   // 512
#define NCTA_FIN  512

__device__ double       d_loss_acc;     // zero-init; reset by last fin CTA
__device__ unsigned int d_ticket;
__device__ uint2        d_part[2 * NVEC];   // per-(half, vec) best (distbits, k)

typedef unsigned long long ull;

__device__ __forceinline__ void fma2(ull& d, ull a, ull b) {
    asm("fma.rn.f32x2 %0, %1, %2, %0;" : "+l"(d) : "l"(a), "l"(b));
}
__device__ __forceinline__ void add2(ull& d, ull a) {
    asm("add.rn.f32x2 %0, %0, %1;" : "+l"(d) : "l"(a));
}
__device__ __forceinline__ float2 unpack2(ull v) {
    float2 r; asm("mov.b64 {%0, %1}, %2;" : "=f"(r.x), "=f"(r.y) : "l"(v)); return r;
}
__device__ __forceinline__ ull pack2(float lo, float hi) {
    ull v; asm("mov.b64 %0, {%1, %2};" : "=l"(v) : "f"(lo), "f"(hi)); return v;
}

// Main: codes-in-registers. blockIdx = vecblock*2 + half. Thread owns codes
// c0 = half*512 + 2*tid and c0+1 (warp = 64 contiguous ascending codes).
// z vectors stream through SMEM; every LDS.128 is a warp-wide broadcast
// serving 64 codes of fma2. Dot arithmetic is bit-identical to the proven
// R3/R7 kernel: chain c = pairs p===c (mod 4) ascending (fma2 operand swap is
// exact by commutativity), add2 tree, fadd(lo,hi), fma(-2,dot,fadd(z2,e2)).
__global__ __launch_bounds__(256, 1)
void vq_main(const float* __restrict__ z, const float* __restrict__ cb) {
    __shared__ ull   zpt[128 * 34];      // [v][34] (pad: 4-way STS, 16B-aligned)
    __shared__ float z2s[128];
    __shared__ uint2 wres[8 * 128];      // per-warp per-vector best

    const int tid  = threadIdx.x, lane = tid & 31, w = tid >> 5;
    const int half = blockIdx.x & 1;
    const int vb   = blockIdx.x >> 1;
    const int c0   = half * 512 + 2 * tid;

    // ---- own 2 code rows in registers (pairs), plus proven-order e2 ----
    ull cr0[32], cr1[32];
    {
        const ulonglong2* p0 = reinterpret_cast<const ulonglong2*>(cb + c0 * E_DIM);
        const ulonglong2* p1 = reinterpret_cast<const ulonglong2*>(cb + (c0 + 1) * E_DIM);
#pragma unroll
        for (int i = 0; i < 16; i++) {
            ulonglong2 t0 = p0[i]; cr0[2 * i] = t0.x; cr0[2 * i + 1] = t0.y;
            ulonglong2 t1 = p1[i]; cr1[2 * i] = t1.x; cr1[2 * i + 1] = t1.y;
        }
    }
    float e20 = 0.f, e21 = 0.f;
    {
        const float4* r0 = reinterpret_cast<const float4*>(cb + c0 * E_DIM);
        const float4* r1 = reinterpret_cast<const float4*>(cb + (c0 + 1) * E_DIM);
#pragma unroll
        for (int i = 0; i < 16; i++) {
            float4 v = r0[i];
            e20 += v.x * v.x + v.y * v.y + v.z * v.z + v.w * v.w;
        }
#pragma unroll
        for (int i = 0; i < 16; i++) {
            float4 v = r1[i];
            e21 += v.x * v.x + v.y * v.y + v.z * v.z + v.w * v.w;
        }
    }

#pragma unroll 1
    for (int tile = 0; tile < 2; tile++) {
        const int vbase = vb * VB + tile * 128;
        __syncthreads();                       // zpt free from previous tile
        if (tid < 128) {                       // owner loads vector tid
            int vid = vbase + tid;
            int b = ((vid >> 12) * E_DIM * 4096) + (vid & 4095);
            float s = 0.f;
#pragma unroll
            for (int p = 0; p < 32; p++) {
                float lo = z[b + (2 * p) * 4096];
                float hi = z[b + (2 * p + 1) * 4096];
                s = __fadd_rn(s, __fadd_rn(__fmul_rn(lo, lo), __fmul_rn(hi, hi)));
                zpt[tid * 34 + p] = pack2(lo, hi);
            }
            z2s[tid] = s;                      // proven pair-sequential z2
        }
        __syncthreads();

#pragma unroll 1
        for (int v = 0; v < 128; v++) {
            const ulonglong2* zb = reinterpret_cast<const ulonglong2*>(zpt + v * 34);
            float z2v = z2s[v];
            ull a0 = 0, a1 = 0, a2 = 0, a3 = 0;    // code c0 chains
            ull b0 = 0, b1 = 0, b2 = 0, b3 = 0;    // code c0+1 chains
#pragma unroll
            for (int g = 0; g < 8; g++) {          // 2 LDS.128 + 8 fma2 per g
                ulonglong2 q0 = zb[2 * g];         // z pairs 4g, 4g+1
                ulonglong2 q1 = zb[2 * g + 1];     // z pairs 4g+2, 4g+3
                fma2(a0, cr0[4 * g + 0], q0.x);
                fma2(b0, cr1[4 * g + 0], q0.x);
                fma2(a1, cr0[4 * g + 1], q0.y);
                fma2(b1, cr1[4 * g + 1], q0.y);
                fma2(a2, cr0[4 * g + 2], q1.x);
                fma2(b2, cr1[4 * g + 2], q1.x);
                fma2(a3, cr0[4 * g + 3], q1.y);
                fma2(b3, cr1[4 * g + 3], q1.y);
            }
            add2(a0, a1); add2(a2, a3); add2(a0, a2);
            add2(b0, b1); add2(b2, b3); add2(b0, b2);
            float2 s0 = unpack2(a0), s1 = unpack2(b0);
            float dot0 = __fadd_rn(s0.x, s0.y);
            float dot1 = __fadd_rn(s1.x, s1.y);
            float d0 = __fmaf_rn(-2.f, dot0, __fadd_rn(z2v, e20));
            float d1 = __fmaf_rn(-2.f, dot1, __fadd_rn(z2v, e21));
            float bd = d0; int bk = c0;            // strict <, ascending k
            if (d1 < bd) { bd = d1; bk = c0 + 1; }
            // warp lexicographic (dist, lowest k) reduce == first-occurrence
#pragma unroll
            for (int o = 16; o; o >>= 1) {
                float od = __shfl_xor_sync(0xFFFFFFFFu, bd, o);
                int   ok = __shfl_xor_sync(0xFFFFFFFFu, bk, o);
                if (od < bd || (od == bd && ok < bk)) { bd = od; bk = ok; }
            }
            if (lane == 0)
                wres[w * 128 + v] = make_uint2(__float_as_uint(bd), (unsigned)bk);
        }
        __syncthreads();
        if (tid < 128) {                       // merge 8 warps, publish
            uint2 e = wres[tid];
            float bd = __uint_as_float(e.x);
            int   bk = (int)e.y;
#pragma unroll
            for (int ww = 1; ww < 8; ww++) {
                uint2 e2 = wres[ww * 128 + tid];
                float od = __uint_as_float(e2.x);
                int   ok = (int)e2.y;
                if (od < bd || (od == bd && ok < bk)) { bd = od; bk = ok; }
            }
            d_part[half * NVEC + vbase + tid] =
                make_uint2(__float_as_uint(bd), (unsigned)bk);
        }
    }
}

// Final: merge halves (half-0 k's are smaller -> tie goes to lower k),
// gather winner, write vq, accumulate loss, ticket finalize.
__global__ __launch_bounds__(128, 8)
void vq_fin(const float* __restrict__ z, const float* __restrict__ cb,
            float* __restrict__ out_vq, float* __restrict__ out_loss,
            int has_loss) {
    const int tid = threadIdx.x;
    const int vid = blockIdx.x * 128 + tid;
    uint2 p0 = d_part[vid], p1 = d_part[NVEC + vid];
    float d0 = __uint_as_float(p0.x), d1 = __uint_as_float(p1.x);
    int k = (int)p0.y;
    if (d1 < d0) k = (int)p1.y;
    const int b = ((vid >> 12) * E_DIM * 4096) + (vid & 4095);
    const float2* er = reinterpret_cast<const float2*>(cb + k * E_DIM);
    float local = 0.f;
#pragma unroll
    for (int i = 0; i < E_DIM / 2; i++) {
        float2 e = __ldg(&er[i]);
        float z0 = z[b + (2 * i) * 4096];
        float z1 = z[b + (2 * i + 1) * 4096];
        float q0 = e.x - z0, q1 = e.y - z1;
        local += q0 * q0 + q1 * q1;
        out_vq[b + (2 * i)     * 4096] = e.x;
        out_vq[b + (2 * i + 1) * 4096] = e.y;
    }
#pragma unroll
    for (int o = 16; o; o >>= 1)
        local += __shfl_xor_sync(0xFFFFFFFFu, local, o);
    if ((tid & 31) == 0)
        atomicAdd(&d_loss_acc, (double)local);

    __syncthreads();
    if (tid == 0) {
        __threadfence();
        unsigned int done = atomicAdd(&d_ticket, 1u);
        if (done == (unsigned int)(NCTA_FIN - 1)) {
            if (has_loss)
                *out_loss = (float)(1.25 * d_loss_acc / (double)NPIX);
            d_loss_acc = 0.0;
            d_ticket   = 0u;
            __threadfence();
        }
    }
}

extern "C" void kernel_launch(void* const* d_in, const int* in_sizes, int n_in,
                              void* d_out, int out_size) {
    // metadata order: z [16,64,64,64] fp32, codebook [1024,64] fp32.
    const float* z  = (const float*)d_in[0];
    const float* cb = (const float*)d_in[1];
    if (n_in >= 2 && in_sizes[0] == K_DIM * E_DIM && in_sizes[1] == NPIX) {
        const float* t = z; z = cb; cb = t;   // defensive: inputs swapped
    }

    float* out = (float*)d_out;
    int voff = out_size - NPIX;            // 1 if scalar loss precedes vq_out
    if (voff < 0) voff = 0;
    float* out_vq = out + voff;

    vq_main<<<NCTA_MAIN, 256>>>(z, cb);
    vq_fin<<<NCTA_FIN, 128>>>(z, cb, out_vq, out, voff > 0 ? 1 : 0);
}

// round 16
// speedup vs baseline: 1.5609x; 1.5440x over previous
#include <cuda_runtime.h>
#include <cuda_bf16.h>

#define K_DIM 1024
#define E_DIM 64
#define NVEC  (16 * 64 * 64)        // 65536 vectors
#define NPIX  (16 * 64 * 64 * 64)   // 4194304 output elements (vq part)
#define KC    256                   // codebook entries per smem chunk
#define NCH   (K_DIM / KC)          // 4 chunks
#define NCTA  (NVEC / 256)          // 256 CTAs, 128 thr, T=2 vectors/thread

// dynamic SMEM: [0,65536) codebook chunk f32, [65536,66560) e2 chunk f32
#define SMEM_TOTAL (KC * E_DIM * 4 + KC * 4)

__device__ double       d_loss_acc;   // zero-init; reset by last CTA each call
__device__ unsigned int d_ticket;     // zero-init; reset by last CTA each call

typedef unsigned long long ull;

// ---- packed f32x2 helpers (sm_103a) ----
__device__ __forceinline__ void fma2(ull& d, ull a, ull b) {
    asm("fma.rn.f32x2 %0, %1, %2, %0;" : "+l"(d) : "l"(a), "l"(b));
}
__device__ __forceinline__ void add2(ull& d, ull a) {
    asm("add.rn.f32x2 %0, %0, %1;" : "+l"(d) : "l"(a));
}
__device__ __forceinline__ float2 unpack2(ull v) {
    float2 r; asm("mov.b64 {%0, %1}, %2;" : "=f"(r.x), "=f"(r.y) : "l"(v)); return r;
}
__device__ __forceinline__ ull pack2(float lo, float hi) {
    ull v; asm("mov.b64 %0, {%1, %2};" : "=l"(v) : "f"(lo), "f"(hi)); return v;
}

// EXACT R7 main-loop body (bit-identical arithmetic: 16-chain unroll-2,
// 4-chain tree per (vec,code), dot=fadd(lo,hi), dist=fma(-2,dot,fadd(z2,e2)),
// strict < ascending k), fused into ONE launch (in-chunk e2 + ticket finalize)
// with KC=256 to halve sync rounds. No pipelining (R13 showed the reg cost
// cancels the gain).
__global__ __launch_bounds__(128, 2)
void vq_kernel(const float* __restrict__ z,
               const float* __restrict__ cb,
               float* __restrict__ out_vq,
               float* __restrict__ out_loss,
               int has_loss) {
    extern __shared__ char sm[];
    float* sh_cb = reinterpret_cast<float*>(sm);
    float* sh_e2 = reinterpret_cast<float*>(sm + KC * E_DIM * 4);

    const int tid = threadIdx.x;
    const int n0  = blockIdx.x * 256 + tid;     // vector ids n0 and n0+128
    const int n1  = n0 + 128;
    const int base0 = (n0 >> 12) * (E_DIM * 4096) + (n0 & 4095);
    const int base1 = (n1 >> 12) * (E_DIM * 4096) + (n1 & 4095);

    // Both z rows in registers as packed f32x2.
    ull zr0[E_DIM / 2], zr1[E_DIM / 2];
#pragma unroll
    for (int i = 0; i < E_DIM / 2; i++) {
        zr0[i] = pack2(z[base0 + (2 * i) * 4096], z[base0 + (2 * i + 1) * 4096]);
        zr1[i] = pack2(z[base1 + (2 * i) * 4096], z[base1 + (2 * i + 1) * 4096]);
    }

    // ||z||^2 fp32, sequential pair order (reference-matching rounding anchor).
    float z20 = 0.f, z21 = 0.f;
#pragma unroll
    for (int i = 0; i < E_DIM / 2; i++) {
        float2 v0 = unpack2(zr0[i]);
        float2 v1 = unpack2(zr1[i]);
        z20 = __fadd_rn(z20, __fadd_rn(__fmul_rn(v0.x, v0.x), __fmul_rn(v0.y, v0.y)));
        z21 = __fadd_rn(z21, __fadd_rn(__fmul_rn(v1.x, v1.x), __fmul_rn(v1.y, v1.y)));
    }

    float best0 = 3.4e38f, best1 = 3.4e38f;
    int   bidx0 = 0,       bidx1 = 0;

    for (int k0 = 0; k0 < K_DIM; k0 += KC) {
        __syncthreads();
        // Cooperative chunk load: KC*64 floats = 4096 float4 / 128 threads
        {
            const float4* src = reinterpret_cast<const float4*>(cb + k0 * E_DIM);
            float4* dst = reinterpret_cast<float4*>(sh_cb);
#pragma unroll
            for (int i = 0; i < (KC * E_DIM / 4) / 128; i++)
                dst[tid + i * 128] = src[tid + i * 128];
        }
        __syncthreads();
        // e2 rows tid, tid+128: float4-sequential (proven bit-identical).
#pragma unroll
        for (int rr = 0; rr < KC / 128; rr++) {
            int r = tid + rr * 128;
            const float4* rp = reinterpret_cast<const float4*>(sh_cb + r * E_DIM);
            float s = 0.f;
#pragma unroll
            for (int i = 0; i < E_DIM / 4; i++) {
                float4 v = rp[i];
                s += v.x * v.x + v.y * v.y + v.z * v.z + v.w * v.w;
            }
            sh_e2[r] = s;
        }
        __syncthreads();

#pragma unroll 1
        for (int j = 0; j < KC; j += 2) {
            const ulonglong2* eA =
                reinterpret_cast<const ulonglong2*>(sh_cb + j * E_DIM);
            const ulonglong2* eB =
                reinterpret_cast<const ulonglong2*>(sh_cb + (j + 1) * E_DIM);
            // 16 independent chains (2 vec x 2 codes x 4 chains); per-(vec,code)
            // tree identical to rounds 3/7.
            ull a0 = 0, a1 = 0, a2 = 0, a3 = 0;   // vec0 x code j
            ull b0 = 0, b1 = 0, b2 = 0, b3 = 0;   // vec1 x code j
            ull c0 = 0, c1 = 0, c2 = 0, c3 = 0;   // vec0 x code j+1
            ull d0 = 0, d1 = 0, d2 = 0, d3 = 0;   // vec1 x code j+1
#pragma unroll
            for (int i = 0; i < 8; i++) {          // 4 LDS.128 + 16 FFMA2 per step
                ulonglong2 xA0 = eA[2 * i];
                ulonglong2 xA1 = eA[2 * i + 1];
                ulonglong2 xB0 = eB[2 * i];
                ulonglong2 xB1 = eB[2 * i + 1];
                fma2(a0, zr0[4 * i + 0], xA0.x);
                fma2(b0, zr1[4 * i + 0], xA0.x);
                fma2(c0, zr0[4 * i + 0], xB0.x);
                fma2(d0, zr1[4 * i + 0], xB0.x);
                fma2(a1, zr0[4 * i + 1], xA0.y);
                fma2(b1, zr1[4 * i + 1], xA0.y);
                fma2(c1, zr0[4 * i + 1], xB0.y);
                fma2(d1, zr1[4 * i + 1], xB0.y);
                fma2(a2, zr0[4 * i + 2], xA1.x);
                fma2(b2, zr1[4 * i + 2], xA1.x);
                fma2(c2, zr0[4 * i + 2], xB1.x);
                fma2(d2, zr1[4 * i + 2], xB1.x);
                fma2(a3, zr0[4 * i + 3], xA1.y);
                fma2(b3, zr1[4 * i + 3], xA1.y);
                fma2(c3, zr0[4 * i + 3], xB1.y);
                fma2(d3, zr1[4 * i + 3], xB1.y);
            }
            add2(a0, a1); add2(a2, a3); add2(a0, a2);
            add2(b0, b1); add2(b2, b3); add2(b0, b2);
            add2(c0, c1); add2(c2, c3); add2(c0, c2);
            add2(d0, d1); add2(d2, d3); add2(d0, d2);
            float2 sA0 = unpack2(a0), sA1 = unpack2(b0);
            float2 sB0 = unpack2(c0), sB1 = unpack2(d0);
            float dotA0 = __fadd_rn(sA0.x, sA0.y);
            float dotA1 = __fadd_rn(sA1.x, sA1.y);
            float dotB0 = __fadd_rn(sB0.x, sB0.y);
            float dotB1 = __fadd_rn(sB1.x, sB1.y);
            float e2A = sh_e2[j], e2B = sh_e2[j + 1];
            // Reference fp32 rounding: (z2 + e2) - 2*dot (fma form, exact 2*dot).
            // Code j strictly before j+1: first-occurrence tie-break preserved.
            float dA0 = __fmaf_rn(-2.0f, dotA0, __fadd_rn(z20, e2A));
            float dA1 = __fmaf_rn(-2.0f, dotA1, __fadd_rn(z21, e2A));
            if (dA0 < best0) { best0 = dA0; bidx0 = k0 + j; }
            if (dA1 < best1) { best1 = dA1; bidx1 = k0 + j; }
            float dB0 = __fmaf_rn(-2.0f, dotB0, __fadd_rn(z20, e2B));
            float dB1 = __fmaf_rn(-2.0f, dotB1, __fadd_rn(z21, e2B));
            if (dB0 < best0) { best0 = dB0; bidx0 = k0 + j + 1; }
            if (dB1 < best1) { best1 = dB1; bidx1 = k0 + j + 1; }
        }
    }

    // Epilogue: gather winning rows (L2-resident), write vq, accumulate loss.
    float local = 0.f;
    {
        const float2* er = reinterpret_cast<const float2*>(cb + bidx0 * E_DIM);
#pragma unroll
        for (int i = 0; i < E_DIM / 2; i++) {
            float2 e  = __ldg(&er[i]);
            float2 zp = unpack2(zr0[i]);
            float q0 = e.x - zp.x, q1 = e.y - zp.y;
            local += q0 * q0 + q1 * q1;
            out_vq[base0 + (2 * i)     * 4096] = e.x;
            out_vq[base0 + (2 * i + 1) * 4096] = e.y;
        }
    }
    {
        const float2* er = reinterpret_cast<const float2*>(cb + bidx1 * E_DIM);
#pragma unroll
        for (int i = 0; i < E_DIM / 2; i++) {
            float2 e  = __ldg(&er[i]);
            float2 zp = unpack2(zr1[i]);
            float q0 = e.x - zp.x, q1 = e.y - zp.y;
            local += q0 * q0 + q1 * q1;
            out_vq[base1 + (2 * i)     * 4096] = e.x;
            out_vq[base1 + (2 * i + 1) * 4096] = e.y;
        }
    }

    // warp reduce + one double atomic per warp
#pragma unroll
    for (int o = 16; o; o >>= 1)
        local += __shfl_xor_sync(0xFFFFFFFFu, local, o);
    if ((tid & 31) == 0)
        atomicAdd(&d_loss_acc, (double)local);

    // Last-CTA finalize (self-resetting: deterministic across graph replays).
    __syncthreads();
    if (tid == 0) {
        __threadfence();
        unsigned int done = atomicAdd(&d_ticket, 1u);
        if (done == (unsigned int)(NCTA - 1)) {
            if (has_loss)
                *out_loss = (float)(1.25 * d_loss_acc / (double)NPIX);
            d_loss_acc = 0.0;
            d_ticket   = 0u;
            __threadfence();
        }
    }
}

extern "C" void kernel_launch(void* const* d_in, const int* in_sizes, int n_in,
                              void* d_out, int out_size) {
    // metadata order: z [16,64,64,64] fp32, codebook [1024,64] fp32.
    const float* z  = (const float*)d_in[0];
    const float* cb = (const float*)d_in[1];
    if (n_in >= 2 && in_sizes[0] == K_DIM * E_DIM && in_sizes[1] == NPIX) {
        const float* t = z; z = cb; cb = t;   // defensive: inputs swapped
    }

    float* out = (float*)d_out;
    int voff = out_size - NPIX;            // 1 if scalar loss precedes vq_out
    if (voff < 0) voff = 0;
    float* out_vq = out + voff;

    cudaFuncSetAttribute(vq_kernel,
                         cudaFuncAttributeMaxDynamicSharedMemorySize, SMEM_TOTAL);

    vq_kernel<<<NCTA, 128, SMEM_TOTAL>>>(z, cb, out_vq, out, voff > 0 ? 1 : 0);
}

// round 17
// speedup vs baseline: 1.6163x; 1.0355x over previous
#include <cuda_runtime.h>
#include <cuda_bf16.h>
#include <cstdint>

#define K_DIM 1024
#define E_DIM 64
#define NVEC  (16 * 64 * 64)        // 65536 vectors
#define NPIX  (16 * 64 * 64 * 64)   // 4194304 output elements (vq part)
#define KC    128                   // codebook entries per smem chunk
#define KHALF 512                   // codes per split-K half
#define NCTA_MAIN ((NVEC / 256) * 2)   // 512: (vec-block, half)
#define NCTA_FIN  (NVEC / 128)         // 512

__device__ double       d_loss_acc;   // zeroed by e2_kernel; reset by ticket
__device__ unsigned int d_ticket;
__device__ float        d_e2[K_DIM];
__device__ uint2        d_part[2 * NVEC];   // per-(half, vec): (distbits, k)

typedef unsigned long long ull;

// ---- packed f32x2 helpers (sm_103a) ----
__device__ __forceinline__ void fma2(ull& d, ull a, ull b) {
    asm("fma.rn.f32x2 %0, %1, %2, %0;" : "+l"(d) : "l"(a), "l"(b));
}
__device__ __forceinline__ void add2(ull& d, ull a) {
    asm("add.rn.f32x2 %0, %0, %1;" : "+l"(d) : "l"(a));
}
__device__ __forceinline__ float2 unpack2(ull v) {
    float2 r; asm("mov.b64 {%0, %1}, %2;" : "=f"(r.x), "=f"(r.y) : "l"(v)); return r;
}
__device__ __forceinline__ ull pack2(float lo, float hi) {
    ull v; asm("mov.b64 %0, {%1, %2};" : "=l"(v) : "f"(lo), "f"(hi)); return v;
}

// ||e_k||^2 (proven float4-sequential order); also zeroes the loss accumulator.
__global__ void e2_kernel(const float* __restrict__ cb) {
    if (blockIdx.x == 0 && threadIdx.x == 0) d_loss_acc = 0.0;
    int k = blockIdx.x * blockDim.x + threadIdx.x;
    if (k < K_DIM) {
        const float4* r = reinterpret_cast<const float4*>(cb + k * E_DIM);
        float s = 0.f;
#pragma unroll
        for (int i = 0; i < E_DIM / 4; i++) {
            float4 v = r[i];
            s += v.x * v.x + v.y * v.y + v.z * v.z + v.w * v.w;
        }
        d_e2[k] = s;
    }
}

// Split-K main: EXACT R7 body (bit-identical per-code arithmetic: 16-chain
// unroll-2, 4-chain tree, dot=fadd(lo,hi), dist=fma(-2,dot,fadd(z2,e2)),
// strict < ascending k) but each CTA scans only one 512-code half. Doubles
// warp count to 2048 (3.46/SMSP) at unchanged per-thread registers; (128,3)
// admits 3 CTAs/SM (body compiled to 168 regs in R9).
__global__ __launch_bounds__(128, 3)
void vq_split(const float* __restrict__ z, const float* __restrict__ cb) {
    __shared__ float sh_cb[KC * E_DIM];   // 32 KB
    __shared__ float sh_e2[KC];

    const int tid  = threadIdx.x;
    const int half = blockIdx.x & 1;
    const int vb   = blockIdx.x >> 1;
    const int n0   = vb * 256 + tid;            // vector ids n0 and n0+128
    const int n1   = n0 + 128;
    const int base0 = (n0 >> 12) * (E_DIM * 4096) + (n0 & 4095);
    const int base1 = (n1 >> 12) * (E_DIM * 4096) + (n1 & 4095);

    // Both z rows in registers as packed f32x2.
    ull zr0[E_DIM / 2], zr1[E_DIM / 2];
#pragma unroll
    for (int i = 0; i < E_DIM / 2; i++) {
        zr0[i] = pack2(z[base0 + (2 * i) * 4096], z[base0 + (2 * i + 1) * 4096]);
        zr1[i] = pack2(z[base1 + (2 * i) * 4096], z[base1 + (2 * i + 1) * 4096]);
    }

    // ||z||^2 fp32, sequential pair order (reference-matching rounding anchor).
    float z20 = 0.f, z21 = 0.f;
#pragma unroll
    for (int i = 0; i < E_DIM / 2; i++) {
        float2 v0 = unpack2(zr0[i]);
        float2 v1 = unpack2(zr1[i]);
        z20 = __fadd_rn(z20, __fadd_rn(__fmul_rn(v0.x, v0.x), __fmul_rn(v0.y, v0.y)));
        z21 = __fadd_rn(z21, __fadd_rn(__fmul_rn(v1.x, v1.x), __fmul_rn(v1.y, v1.y)));
    }

    float best0 = 3.4e38f, best1 = 3.4e38f;
    int   bidx0 = 0,       bidx1 = 0;

    const int kbeg = half * KHALF;
    for (int k0 = kbeg; k0 < kbeg + KHALF; k0 += KC) {
        __syncthreads();
        // Cooperative chunk load: KC*64 floats = 2048 float4 / 128 threads
        const float4* src = reinterpret_cast<const float4*>(cb + k0 * E_DIM);
        float4* dst = reinterpret_cast<float4*>(sh_cb);
#pragma unroll
        for (int i = 0; i < (KC * E_DIM / 4) / 128; i++)
            dst[tid + i * 128] = src[tid + i * 128];
        sh_e2[tid] = d_e2[k0 + tid];              // KC == blockDim
        __syncthreads();

#pragma unroll 1
        for (int j = 0; j < KC; j += 2) {
            const ulonglong2* eA =
                reinterpret_cast<const ulonglong2*>(sh_cb + j * E_DIM);
            const ulonglong2* eB =
                reinterpret_cast<const ulonglong2*>(sh_cb + (j + 1) * E_DIM);
            // 16 independent chains (2 vec x 2 codes x 4 chains); per-(vec,code)
            // tree identical to rounds 3/7.
            ull a0 = 0, a1 = 0, a2 = 0, a3 = 0;   // vec0 x code j
            ull b0 = 0, b1 = 0, b2 = 0, b3 = 0;   // vec1 x code j
            ull c0 = 0, c1 = 0, c2 = 0, c3 = 0;   // vec0 x code j+1
            ull d0 = 0, d1 = 0, d2 = 0, d3 = 0;   // vec1 x code j+1
#pragma unroll
            for (int i = 0; i < 8; i++) {          // 4 LDS.128 + 16 FFMA2 per step
                ulonglong2 xA0 = eA[2 * i];
                ulonglong2 xA1 = eA[2 * i + 1];
                ulonglong2 xB0 = eB[2 * i];
                ulonglong2 xB1 = eB[2 * i + 1];
                fma2(a0, zr0[4 * i + 0], xA0.x);
                fma2(b0, zr1[4 * i + 0], xA0.x);
                fma2(c0, zr0[4 * i + 0], xB0.x);
                fma2(d0, zr1[4 * i + 0], xB0.x);
                fma2(a1, zr0[4 * i + 1], xA0.y);
                fma2(b1, zr1[4 * i + 1], xA0.y);
                fma2(c1, zr0[4 * i + 1], xB0.y);
                fma2(d1, zr1[4 * i + 1], xB0.y);
                fma2(a2, zr0[4 * i + 2], xA1.x);
                fma2(b2, zr1[4 * i + 2], xA1.x);
                fma2(c2, zr0[4 * i + 2], xB1.x);
                fma2(d2, zr1[4 * i + 2], xB1.x);
                fma2(a3, zr0[4 * i + 3], xA1.y);
                fma2(b3, zr1[4 * i + 3], xA1.y);
                fma2(c3, zr0[4 * i + 3], xB1.y);
                fma2(d3, zr1[4 * i + 3], xB1.y);
            }
            add2(a0, a1); add2(a2, a3); add2(a0, a2);
            add2(b0, b1); add2(b2, b3); add2(b0, b2);
            add2(c0, c1); add2(c2, c3); add2(c0, c2);
            add2(d0, d1); add2(d2, d3); add2(d0, d2);
            float2 sA0 = unpack2(a0), sA1 = unpack2(b0);
            float2 sB0 = unpack2(c0), sB1 = unpack2(d0);
            float dotA0 = __fadd_rn(sA0.x, sA0.y);
            float dotA1 = __fadd_rn(sA1.x, sA1.y);
            float dotB0 = __fadd_rn(sB0.x, sB0.y);
            float dotB1 = __fadd_rn(sB1.x, sB1.y);
            float e2A = sh_e2[j - (k0 - kbeg) + (k0 - kbeg)];   // = sh_e2[j]
            float e2B = sh_e2[j + 1];
            e2A = sh_e2[j];
            // Reference fp32 rounding: (z2 + e2) - 2*dot (fma form, exact 2*dot).
            // Code j strictly before j+1: first-occurrence tie-break preserved.
            float dA0 = __fmaf_rn(-2.0f, dotA0, __fadd_rn(z20, e2A));
            float dA1 = __fmaf_rn(-2.0f, dotA1, __fadd_rn(z21, e2A));
            if (dA0 < best0) { best0 = dA0; bidx0 = k0 + j; }
            if (dA1 < best1) { best1 = dA1; bidx1 = k0 + j; }
            float dB0 = __fmaf_rn(-2.0f, dotB0, __fadd_rn(z20, e2B));
            float dB1 = __fmaf_rn(-2.0f, dotB1, __fadd_rn(z21, e2B));
            if (dB0 < best0) { best0 = dB0; bidx0 = k0 + j + 1; }
            if (dB1 < best1) { best1 = dB1; bidx1 = k0 + j + 1; }
        }
    }

    // Publish this half's partial result (coalesced uint2 stores).
    d_part[half * NVEC + n0] = make_uint2(__float_as_uint(best0), (unsigned)bidx0);
    d_part[half * NVEC + n1] = make_uint2(__float_as_uint(best1), (unsigned)bidx1);
}

// Merge halves (strict <: half-0 wins ties, its k's are smaller ->
// first-occurrence), gather winner, write vq, loss, ticket finalize.
__global__ __launch_bounds__(128, 8)
void vq_fin(const float* __restrict__ z, const float* __restrict__ cb,
            float* __restrict__ out_vq, float* __restrict__ out_loss,
            int has_loss) {
    const int tid = threadIdx.x;
    const int vid = blockIdx.x * 128 + tid;
    uint2 p0 = d_part[vid], p1 = d_part[NVEC + vid];
    float d0 = __uint_as_float(p0.x), d1 = __uint_as_float(p1.x);
    int k = (int)p0.y;
    if (d1 < d0) k = (int)p1.y;
    const int b = ((vid >> 12) * E_DIM * 4096) + (vid & 4095);
    const float2* er = reinterpret_cast<const float2*>(cb + k * E_DIM);
    float local = 0.f;
#pragma unroll
    for (int i = 0; i < E_DIM / 2; i++) {
        float2 e = __ldg(&er[i]);
        float z0 = z[b + (2 * i) * 4096];
        float z1 = z[b + (2 * i + 1) * 4096];
        float q0 = e.x - z0, q1 = e.y - z1;
        local += q0 * q0 + q1 * q1;
        out_vq[b + (2 * i)     * 4096] = e.x;
        out_vq[b + (2 * i + 1) * 4096] = e.y;
    }
#pragma unroll
    for (int o = 16; o; o >>= 1)
        local += __shfl_xor_sync(0xFFFFFFFFu, local, o);
    if ((tid & 31) == 0)
        atomicAdd(&d_loss_acc, (double)local);

    __syncthreads();
    if (tid == 0) {
        __threadfence();
        unsigned int done = atomicAdd(&d_ticket, 1u);
        if (done == (unsigned int)(NCTA_FIN - 1)) {
            if (has_loss)
                *out_loss = (float)(1.25 * d_loss_acc / (double)NPIX);
            d_loss_acc = 0.0;
            d_ticket   = 0u;
            __threadfence();
        }
    }
}

extern "C" void kernel_launch(void* const* d_in, const int* in_sizes, int n_in,
                              void* d_out, int out_size) {
    // metadata order: z [16,64,64,64] fp32, codebook [1024,64] fp32.
    const float* z  = (const float*)d_in[0];
    const float* cb = (const float*)d_in[1];
    if (n_in >= 2 && in_sizes[0] == K_DIM * E_DIM && in_sizes[1] == NPIX) {
        const float* t = z; z = cb; cb = t;   // defensive: inputs swapped
    }

    float* out = (float*)d_out;
    int voff = out_size - NPIX;            // 1 if scalar loss precedes vq_out
    if (voff < 0) voff = 0;
    float* out_vq = out + voff;

    e2_kernel<<<K_DIM / 256, 256>>>(cb);             // also zeroes loss acc
    vq_split<<<NCTA_MAIN, 128>>>(z, cb);             // split-K halves
    vq_fin<<<NCTA_FIN, 128>>>(z, cb, out_vq, out, voff > 0 ? 1 : 0);
}